// round 5
// baseline (speedup 1.0000x reference)
#include <cuda_runtime.h>
#include <cstdint>

// Problem constants (CRF_6262062317593): B=512, S=512, T=128
#define CRF_B 512
#define CRF_S 512
#define CRF_T 128
#define SHIFT 5.0f   // ~log(T): per-step normalizer folded into exp(emission)

// Scratch (device globals: allocations are forbidden).
__device__ float g_diff[CRF_B];
__device__ int   g_arrived = 0;   // grid-finish ticket (reset by last CTA)

// ---- packed f32x2 helpers (Blackwell FFMA2) ----
__device__ __forceinline__ unsigned long long pk2(float lo, float hi) {
    unsigned long long r;
    asm("mov.b64 %0, {%1, %2};" : "=l"(r) : "f"(lo), "f"(hi));
    return r;
}
__device__ __forceinline__ void upk2(float& lo, float& hi, unsigned long long v) {
    asm("mov.b64 {%0, %1}, %2;" : "=f"(lo), "=f"(hi) : "l"(v));
}
__device__ __forceinline__ void fma2(unsigned long long& acc,
                                     unsigned long long a,
                                     unsigned long long b) {
    asm("fma.rn.f32x2 %0, %1, %2, %0;" : "+l"(acc) : "l"(a), "l"(b));
}

// ---------------------------------------------------------------------------
// Single fused kernel: per-CTA dtype detect -> exp-space forward recursion
// (2 batches per CTA) -> gold score -> grid-finish deterministic reduction.
// ---------------------------------------------------------------------------
__global__ __launch_bounds__(CRF_T, 2)
void crf_fused_kernel(const float* __restrict__ em,       // (B,S,T) f32
                      const void*  __restrict__ tags,     // (B,S) i32 or i64
                      const void*  __restrict__ mask,     // (B,S) i32 or u8
                      const float* __restrict__ startT,   // (T)
                      const float* __restrict__ endT,     // (T)
                      const float* __restrict__ trans,    // (T,T)
                      float* __restrict__ out)            // scalar
{
    const int b0 = 2 * blockIdx.x;
    const int b1 = b0 + 1;
    const int j = threadIdx.x;
    const int lane = j & 31;
    const int warp = j >> 5;

    const float* __restrict__ emb0 = em + (size_t)b0 * CRF_S * CRF_T;
    const float* __restrict__ emb1 = em + (size_t)b1 * CRF_S * CRF_T;

    __shared__ __align__(16) float sV0[2][CRF_T];
    __shared__ __align__(16) float sV1[2][CRF_T];
    __shared__ float         sRed[8];
    __shared__ float         sPart[CRF_T];
    __shared__ int           sCnt[CRF_T];
    __shared__ unsigned char sMask0[CRF_S];
    __shared__ unsigned char sMask1[CRF_S];
    __shared__ short         sTags0[CRF_S];
    __shared__ short         sTags1[CRF_S];
    __shared__ int           sDet[4];       // [0..1] zero-counts, [2..3] big-counts
    __shared__ int           sLast;

    // ---- inline dtype detect (each CTA independently; reads hit L2) ----
    if (j < 64) {
        const unsigned int* tw = (const unsigned int*)tags;
        const unsigned int* mw = (const unsigned int*)mask;
        const int zero = (tw[2 * j + 1] == 0u) ? 1 : 0;
        const int big  = (mw[j] > 1u) ? 1 : 0;
        const unsigned zm = __ballot_sync(0xffffffffu, zero);
        const unsigned bm = __ballot_sync(0xffffffffu, big);
        if (lane == 0) {
            sDet[warp] = __popc(zm);
            sDet[2 + warp] = __popc(bm);
        }
    }
    __syncthreads();
    const int tags_is64 = ((sDet[0] + sDet[1]) >= 48);
    const int mask_is32 = ((sDet[2] + sDet[3]) == 0);

    // ---- stage mask + tags with detected widths ----
    if (mask_is32) {
        const int* m0 = (const int*)mask + (size_t)b0 * CRF_S;
        const int* m1 = (const int*)mask + (size_t)b1 * CRF_S;
        for (int s = j; s < CRF_S; s += CRF_T) {
            sMask0[s] = (m0[s] != 0);
            sMask1[s] = (m1[s] != 0);
        }
    } else {
        const unsigned char* m0 = (const unsigned char*)mask + (size_t)b0 * CRF_S;
        const unsigned char* m1 = (const unsigned char*)mask + (size_t)b1 * CRF_S;
        for (int s = j; s < CRF_S; s += CRF_T) {
            sMask0[s] = (m0[s] != 0);
            sMask1[s] = (m1[s] != 0);
        }
    }
    if (tags_is64) {
        const long long* t0 = (const long long*)tags + (size_t)b0 * CRF_S;
        const long long* t1 = (const long long*)tags + (size_t)b1 * CRF_S;
        for (int s = j; s < CRF_S; s += CRF_T) {
            sTags0[s] = (short)t0[s];
            sTags1[s] = (short)t1[s];
        }
    } else {
        const int* t0 = (const int*)tags + (size_t)b0 * CRF_S;
        const int* t1 = (const int*)tags + (size_t)b1 * CRF_S;
        for (int s = j; s < CRF_S; s += CRF_T) {
            sTags0[s] = (short)t0[s];
            sTags1[s] = (short)t1[s];
        }
    }

    // ---- E column j as 64 packed f32x2 registers ----
    unsigned long long Epk[CRF_T / 2];
#pragma unroll
    for (int k = 0; k < CRF_T / 2; k++) {
        const float e0 = __expf(trans[(2 * k) * CRF_T + j]);
        const float e1 = __expf(trans[(2 * k + 1) * CRF_T + j]);
        Epk[k] = pk2(e0, e1);
    }

    // ---- t = 0 init ----
    const float m00 = startT[0] + emb0[0];
    const float m01 = startT[0] + emb1[0];
    const float stj = startT[j];
    float v0 = __expf(stj + emb0[j] - m00);
    float v1 = __expf(stj + emb1[j] - m01);
    float logZ0 = m00, logZ1 = m01;
    int   nstep0 = 0, nstep1 = 0;

    sV0[0][j] = v0;
    sV1[0][j] = v1;

    float w0 = __expf(emb0[CRF_T + j] - SHIFT);
    float w1 = __expf(emb1[CRF_T + j] - SHIFT);
    __syncthreads();

    for (int s = 1; s < CRF_S; s++) {
        const int p = (s + 1) & 1;
        const int q = s & 1;

        // branchless prefetch of next emissions (clamped; unused at s=S-1)
        const int sn = (s + 1 < CRF_S) ? (s + 1) : (CRF_S - 1);
        const float en0 = emb0[(size_t)sn * CRF_T + j];
        const float en1 = emb1[(size_t)sn * CRF_T + j];
        const int mk0 = sMask0[s];
        const int mk1 = sMask1[s];

        const ulonglong2* r0 = (const ulonglong2*)sV0[p];
        const ulonglong2* r1 = (const ulonglong2*)sV1[p];
        unsigned long long a0 = 0ull, a1 = 0ull;
        unsigned long long c0 = 0ull, c1 = 0ull;
#pragma unroll
        for (int i = 0; i < CRF_T / 4; i++) {
            const ulonglong2 x = r0[i];
            const ulonglong2 y = r1[i];
            fma2(a0, x.x, Epk[2 * i + 0]);
            fma2(a1, x.y, Epk[2 * i + 1]);
            fma2(c0, y.x, Epk[2 * i + 0]);
            fma2(c1, y.y, Epk[2 * i + 1]);
        }
        float a0l, a0h, a1l, a1h, c0l, c0h, c1l, c1h;
        upk2(a0l, a0h, a0); upk2(a1l, a1h, a1);
        upk2(c0l, c0h, c0); upk2(c1l, c1h, c1);
        const float dot0 = (a0l + a0h) + (a1l + a1h);
        const float dot1 = (c0l + c0h) + (c1l + c1h);

        float vn0 = mk0 ? dot0 * w0 : v0;
        float vn1 = mk1 ? dot1 * w1 : v1;
        nstep0 += mk0;
        nstep1 += mk1;

        if ((s & 7) == 0) {            // periodic rescale
            const float cc0 = sV0[p][0];
            const float cc1 = sV1[p][0];
            vn0 *= __fdividef(1.0f, cc0);
            vn1 *= __fdividef(1.0f, cc1);
            logZ0 += __logf(cc0);
            logZ1 += __logf(cc1);
        }

        sV0[q][j] = vn0;
        sV1[q][j] = vn1;
        v0 = vn0;
        v1 = vn1;

        w0 = __expf(en0 - SHIFT);
        w1 = __expf(en1 - SHIFT);
        __syncthreads();
    }
    logZ0 += SHIFT * (float)nstep0;
    logZ1 += SHIFT * (float)nstep1;

    // ---- final: fwd_b = log(sum_j v_j * exp(end_j)) + logZ_b ----
    const float ej = __expf(endT[j]);
    float t0 = v0 * ej;
    float t1 = v1 * ej;
#pragma unroll
    for (int off = 16; off; off >>= 1) {
        t0 += __shfl_xor_sync(0xffffffffu, t0, off);
        t1 += __shfl_xor_sync(0xffffffffu, t1, off);
    }
    if (lane == 0) { sRed[warp] = t0; sRed[4 + warp] = t1; }
    __syncthreads();
    const float fwd0 = __logf((sRed[0] + sRed[1]) + (sRed[2] + sRed[3])) + logZ0;
    const float fwd1 = __logf((sRed[4] + sRed[5]) + (sRed[6] + sRed[7])) + logZ1;

    // ---- gold scores (fixed-order tree reduce) ----
#pragma unroll
    for (int which = 0; which < 2; which++) {
        const unsigned char* mA = which ? sMask1 : sMask0;
        const short*         tA = which ? sTags1 : sTags0;
        const float* __restrict__ eA = which ? emb1 : emb0;

        float part = 0.f;
        int cnt = 0;
        for (int s = j; s < CRF_S; s += CRF_T) {
            const int mk = mA[s] ? 1 : 0;
            cnt += mk;
            if (s >= 1 && mk) {
                const int tp = (int)tA[s - 1];
                const int tc = (int)tA[s];
                part += trans[tp * CRF_T + tc] + eA[(size_t)s * CRF_T + tc];
            }
        }
        __syncthreads();
        sPart[j] = part;
        sCnt[j]  = cnt;
        __syncthreads();
#pragma unroll
        for (int stride = CRF_T / 2; stride > 0; stride >>= 1) {
            if (j < stride) {
                sPart[j] += sPart[j + stride];
                sCnt[j]  += sCnt[j + stride];
            }
            __syncthreads();
        }
        if (j == 0) {
            const int tg0 = (int)tA[0];
            float gold = sPart[0] + startT[tg0] + eA[tg0];
            const int seq_end = sCnt[0] - 1;
            gold += endT[(int)tA[seq_end]];
            g_diff[which ? b1 : b0] = (which ? fwd1 : fwd0) - gold;
        }
    }

    // ---- grid-finish: last CTA does the deterministic mean ----
    __syncthreads();
    if (j == 0) {
        __threadfence();
        const int ticket = atomicAdd(&g_arrived, 1);
        sLast = (ticket == (CRF_B / 2) - 1);
    }
    __syncthreads();
    if (sLast) {
        __threadfence();  // acquire: all g_diff writes visible
        // 128 threads reduce 512 values, fixed order: 4 strided loads each
        float acc = g_diff[j] + g_diff[j + 128] + g_diff[j + 256] + g_diff[j + 384];
        sPart[j] = acc;
        __syncthreads();
#pragma unroll
        for (int stride = CRF_T / 2; stride > 0; stride >>= 1) {
            if (j < stride) sPart[j] += sPart[j + stride];
            __syncthreads();
        }
        if (j == 0) {
            out[0] = sPart[0] * (1.0f / (float)CRF_B);
            g_arrived = 0;   // reset for next graph replay
        }
    }
}

extern "C" void kernel_launch(void* const* d_in, const int* in_sizes, int n_in,
                              void* d_out, int out_size)
{
    const float* emissions = (const float*)d_in[0];
    const void*  tags      = d_in[1];
    const void*  mask      = d_in[2];
    const float* startT    = (const float*)d_in[3];
    const float* endT      = (const float*)d_in[4];
    const float* trans     = (const float*)d_in[5];
    float*       out       = (float*)d_out;

    crf_fused_kernel<<<CRF_B / 2, CRF_T>>>(emissions, tags, mask,
                                           startT, endT, trans, out);
}

// round 6
// speedup vs baseline: 1.0779x; 1.0779x over previous
#include <cuda_runtime.h>
#include <cuda_fp16.h>
#include <cstdint>

// Problem constants (CRF_6262062317593): B=512, S=512, T=128
#define CRF_B 512
#define CRF_S 512
#define CRF_T 128
#define SHIFT 5.0f   // ~log(T): per-step normalizer folded into exp(emission)

// Scratch (device globals: allocations are forbidden).
__device__ float g_diff[CRF_B];
__device__ int   g_arrived = 0;   // grid-finish ticket (reset by last CTA)

__device__ __forceinline__ __half2 u32_as_h2(unsigned int u) {
    return *reinterpret_cast<__half2*>(&u);
}

// ---------------------------------------------------------------------------
// Single fused kernel: per-CTA dtype detect -> fp16 exp-space forward
// recursion (2 batches per CTA) -> gold score -> grid-finish reduction.
// State v lives in smem as fp16 (halves LDS wavefronts vs fp32); E column in
// 64 half2 registers; dot via HFMA2 into 8 short accumulators, combined fp32.
// ---------------------------------------------------------------------------
__global__ __launch_bounds__(CRF_T, 2)
void crf_fused_kernel(const float* __restrict__ em,       // (B,S,T) f32
                      const void*  __restrict__ tags,     // (B,S) i32 or i64
                      const void*  __restrict__ mask,     // (B,S) i32 or u8
                      const float* __restrict__ startT,   // (T)
                      const float* __restrict__ endT,     // (T)
                      const float* __restrict__ trans,    // (T,T)
                      float* __restrict__ out)            // scalar
{
    const int b0 = 2 * blockIdx.x;
    const int b1 = b0 + 1;
    const int j = threadIdx.x;
    const int lane = j & 31;
    const int warp = j >> 5;

    const float* __restrict__ emb0 = em + (size_t)b0 * CRF_S * CRF_T;
    const float* __restrict__ emb1 = em + (size_t)b1 * CRF_S * CRF_T;

    __shared__ __align__(16) __half sV0[2][CRF_T];
    __shared__ __align__(16) __half sV1[2][CRF_T];
    __shared__ float         sRed[8];
    __shared__ float         sPart[CRF_T];
    __shared__ int           sCnt[CRF_T];
    __shared__ unsigned char sMask0[CRF_S];
    __shared__ unsigned char sMask1[CRF_S];
    __shared__ short         sTags0[CRF_S];
    __shared__ short         sTags1[CRF_S];
    __shared__ int           sDet[4];
    __shared__ int           sLast;

    // ---- inline dtype detect (validated R2: mask int32 on this harness) ----
    if (j < 64) {
        const unsigned int* tw = (const unsigned int*)tags;
        const unsigned int* mw = (const unsigned int*)mask;
        const int zero = (tw[2 * j + 1] == 0u) ? 1 : 0;
        const int big  = (mw[j] > 1u) ? 1 : 0;
        const unsigned zm = __ballot_sync(0xffffffffu, zero);
        const unsigned bm = __ballot_sync(0xffffffffu, big);
        if (lane == 0) {
            sDet[warp] = __popc(zm);
            sDet[2 + warp] = __popc(bm);
        }
    }
    __syncthreads();
    const int tags_is64 = ((sDet[0] + sDet[1]) >= 48);
    const int mask_is32 = ((sDet[2] + sDet[3]) == 0);

    // ---- stage mask + tags with detected widths ----
    if (mask_is32) {
        const int* m0 = (const int*)mask + (size_t)b0 * CRF_S;
        const int* m1 = (const int*)mask + (size_t)b1 * CRF_S;
        for (int s = j; s < CRF_S; s += CRF_T) {
            sMask0[s] = (m0[s] != 0);
            sMask1[s] = (m1[s] != 0);
        }
    } else {
        const unsigned char* m0 = (const unsigned char*)mask + (size_t)b0 * CRF_S;
        const unsigned char* m1 = (const unsigned char*)mask + (size_t)b1 * CRF_S;
        for (int s = j; s < CRF_S; s += CRF_T) {
            sMask0[s] = (m0[s] != 0);
            sMask1[s] = (m1[s] != 0);
        }
    }
    if (tags_is64) {
        const long long* t0 = (const long long*)tags + (size_t)b0 * CRF_S;
        const long long* t1 = (const long long*)tags + (size_t)b1 * CRF_S;
        for (int s = j; s < CRF_S; s += CRF_T) {
            sTags0[s] = (short)t0[s];
            sTags1[s] = (short)t1[s];
        }
    } else {
        const int* t0 = (const int*)tags + (size_t)b0 * CRF_S;
        const int* t1 = (const int*)tags + (size_t)b1 * CRF_S;
        for (int s = j; s < CRF_S; s += CRF_T) {
            sTags0[s] = (short)t0[s];
            sTags1[s] = (short)t1[s];
        }
    }

    // ---- E column j as 64 half2 registers: Eh[k] = (E[2k][j], E[2k+1][j]) ----
    __half2 Eh[CRF_T / 2];
#pragma unroll
    for (int k = 0; k < CRF_T / 2; k++) {
        const float e0 = __expf(trans[(2 * k) * CRF_T + j]);
        const float e1 = __expf(trans[(2 * k + 1) * CRF_T + j]);
        Eh[k] = __floats2half2_rn(e0, e1);
    }

    // ---- t = 0 init: v = exp(start + em0 - m0), logZ = m0 ----
    const float m00 = startT[0] + emb0[0];
    const float m01 = startT[0] + emb1[0];
    const float stj = startT[j];
    float v0 = __expf(stj + emb0[j] - m00);
    float v1 = __expf(stj + emb1[j] - m01);
    float logZ0 = m00, logZ1 = m01;
    int   nstep0 = 0, nstep1 = 0;

    sV0[0][j] = __float2half_rn(v0);
    sV1[0][j] = __float2half_rn(v1);

    float w0 = __expf(emb0[CRF_T + j] - SHIFT);
    float w1 = __expf(emb1[CRF_T + j] - SHIFT);
    __syncthreads();

    for (int s = 1; s < CRF_S; s++) {
        const int p = (s + 1) & 1;
        const int q = s & 1;

        // branchless prefetch of next emissions (clamped; unused at s=S-1)
        const int sn = (s + 1 < CRF_S) ? (s + 1) : (CRF_S - 1);
        const float en0 = emb0[(size_t)sn * CRF_T + j];
        const float en1 = emb1[(size_t)sn * CRF_T + j];
        const int mk0 = sMask0[s];
        const int mk1 = sMask1[s];

        // 16 LDS.128 per batch: 128 halves of v (broadcast, conflict-free)
        const uint4* r0 = (const uint4*)sV0[p];
        const uint4* r1 = (const uint4*)sV1[p];
        __half2 A[8], C[8];
#pragma unroll
        for (int k = 0; k < 8; k++) { A[k] = __half2half2(__ushort_as_half(0)); C[k] = A[k]; }
#pragma unroll
        for (int i = 0; i < 16; i++) {
            const uint4 x = r0[i];
            const uint4 y = r1[i];
            A[(4*i+0)&7] = __hfma2(u32_as_h2(x.x), Eh[4*i+0], A[(4*i+0)&7]);
            A[(4*i+1)&7] = __hfma2(u32_as_h2(x.y), Eh[4*i+1], A[(4*i+1)&7]);
            A[(4*i+2)&7] = __hfma2(u32_as_h2(x.z), Eh[4*i+2], A[(4*i+2)&7]);
            A[(4*i+3)&7] = __hfma2(u32_as_h2(x.w), Eh[4*i+3], A[(4*i+3)&7]);
            C[(4*i+0)&7] = __hfma2(u32_as_h2(y.x), Eh[4*i+0], C[(4*i+0)&7]);
            C[(4*i+1)&7] = __hfma2(u32_as_h2(y.y), Eh[4*i+1], C[(4*i+1)&7]);
            C[(4*i+2)&7] = __hfma2(u32_as_h2(y.z), Eh[4*i+2], C[(4*i+2)&7]);
            C[(4*i+3)&7] = __hfma2(u32_as_h2(y.w), Eh[4*i+3], C[(4*i+3)&7]);
        }
        // fp32 combine (fixed order)
        float dot0, dot1;
        {
            float2 f0 = __half22float2(A[0]), f1 = __half22float2(A[1]);
            float2 f2 = __half22float2(A[2]), f3 = __half22float2(A[3]);
            float2 f4 = __half22float2(A[4]), f5 = __half22float2(A[5]);
            float2 f6 = __half22float2(A[6]), f7 = __half22float2(A[7]);
            dot0 = (((f0.x + f0.y) + (f1.x + f1.y)) + ((f2.x + f2.y) + (f3.x + f3.y)))
                 + (((f4.x + f4.y) + (f5.x + f5.y)) + ((f6.x + f6.y) + (f7.x + f7.y)));
            float2 g0 = __half22float2(C[0]), g1 = __half22float2(C[1]);
            float2 g2 = __half22float2(C[2]), g3 = __half22float2(C[3]);
            float2 g4 = __half22float2(C[4]), g5 = __half22float2(C[5]);
            float2 g6 = __half22float2(C[6]), g7 = __half22float2(C[7]);
            dot1 = (((g0.x + g0.y) + (g1.x + g1.y)) + ((g2.x + g2.y) + (g3.x + g3.y)))
                 + (((g4.x + g4.y) + (g5.x + g5.y)) + ((g6.x + g6.y) + (g7.x + g7.y)));
        }

        float vn0 = mk0 ? dot0 * w0 : v0;
        float vn1 = mk1 ? dot1 * w1 : v1;
        nstep0 += mk0;
        nstep1 += mk1;

        if ((s & 3) == 0) {            // rescale every 4 steps (fp16 range)
            const float cc0 = __half2float(sV0[p][0]);
            const float cc1 = __half2float(sV1[p][0]);
            vn0 *= __fdividef(1.0f, cc0);
            vn1 *= __fdividef(1.0f, cc1);
            logZ0 += __logf(cc0);
            logZ1 += __logf(cc1);
        }

        sV0[q][j] = __float2half_rn(vn0);
        sV1[q][j] = __float2half_rn(vn1);
        v0 = vn0;
        v1 = vn1;

        w0 = __expf(en0 - SHIFT);
        w1 = __expf(en1 - SHIFT);
        __syncthreads();
    }
    logZ0 += SHIFT * (float)nstep0;
    logZ1 += SHIFT * (float)nstep1;

    // ---- final: fwd_b = log(sum_j v_j * exp(end_j)) + logZ_b (all fp32) ----
    const float ej = __expf(endT[j]);
    float t0 = v0 * ej;
    float t1 = v1 * ej;
#pragma unroll
    for (int off = 16; off; off >>= 1) {
        t0 += __shfl_xor_sync(0xffffffffu, t0, off);
        t1 += __shfl_xor_sync(0xffffffffu, t1, off);
    }
    if (lane == 0) { sRed[warp] = t0; sRed[4 + warp] = t1; }
    __syncthreads();
    const float fwd0 = __logf((sRed[0] + sRed[1]) + (sRed[2] + sRed[3])) + logZ0;
    const float fwd1 = __logf((sRed[4] + sRed[5]) + (sRed[6] + sRed[7])) + logZ1;

    // ---- gold scores (fp32, fixed-order tree reduce) ----
#pragma unroll
    for (int which = 0; which < 2; which++) {
        const unsigned char* mA = which ? sMask1 : sMask0;
        const short*         tA = which ? sTags1 : sTags0;
        const float* __restrict__ eA = which ? emb1 : emb0;

        float part = 0.f;
        int cnt = 0;
        for (int s = j; s < CRF_S; s += CRF_T) {
            const int mk = mA[s] ? 1 : 0;
            cnt += mk;
            if (s >= 1 && mk) {
                const int tp = (int)tA[s - 1];
                const int tc = (int)tA[s];
                part += trans[tp * CRF_T + tc] + eA[(size_t)s * CRF_T + tc];
            }
        }
        __syncthreads();
        sPart[j] = part;
        sCnt[j]  = cnt;
        __syncthreads();
#pragma unroll
        for (int stride = CRF_T / 2; stride > 0; stride >>= 1) {
            if (j < stride) {
                sPart[j] += sPart[j + stride];
                sCnt[j]  += sCnt[j + stride];
            }
            __syncthreads();
        }
        if (j == 0) {
            const int tg0 = (int)tA[0];
            float gold = sPart[0] + startT[tg0] + eA[tg0];
            const int seq_end = sCnt[0] - 1;
            gold += endT[(int)tA[seq_end]];
            g_diff[which ? b1 : b0] = (which ? fwd1 : fwd0) - gold;
        }
    }

    // ---- grid-finish: last CTA does the deterministic mean ----
    __syncthreads();
    if (j == 0) {
        __threadfence();
        const int ticket = atomicAdd(&g_arrived, 1);
        sLast = (ticket == (CRF_B / 2) - 1);
    }
    __syncthreads();
    if (sLast) {
        __threadfence();
        float acc = g_diff[j] + g_diff[j + 128] + g_diff[j + 256] + g_diff[j + 384];
        sPart[j] = acc;
        __syncthreads();
#pragma unroll
        for (int stride = CRF_T / 2; stride > 0; stride >>= 1) {
            if (j < stride) sPart[j] += sPart[j + stride];
            __syncthreads();
        }
        if (j == 0) {
            out[0] = sPart[0] * (1.0f / (float)CRF_B);
            g_arrived = 0;
        }
    }
}

extern "C" void kernel_launch(void* const* d_in, const int* in_sizes, int n_in,
                              void* d_out, int out_size)
{
    const float* emissions = (const float*)d_in[0];
    const void*  tags      = d_in[1];
    const void*  mask      = d_in[2];
    const float* startT    = (const float*)d_in[3];
    const float* endT      = (const float*)d_in[4];
    const float* trans     = (const float*)d_in[5];
    float*       out       = (float*)d_out;

    crf_fused_kernel<<<CRF_B / 2, CRF_T>>>(emissions, tags, mask,
                                           startT, endT, trans, out);
}

// round 7
// speedup vs baseline: 1.1532x; 1.0699x over previous
#include <cuda_runtime.h>
#include <cuda_fp16.h>
#include <cstdint>

// Problem constants (CRF_6262062317593): B=512, S=512, T=128
#define CRF_B 512
#define CRF_S 512
#define CRF_T 128
#define SHIFT 5.0f   // ~log(T): per-step normalizer folded into exp(emission)

// Scratch (device globals: allocations are forbidden).
__device__ float g_diff[CRF_B];
__device__ int   g_arrived = 0;   // grid-finish ticket (reset by last CTA)

__device__ __forceinline__ __half2 u32_as_h2(unsigned int u) {
    return *reinterpret_cast<__half2*>(&u);
}

// ---------------------------------------------------------------------------
// Fused kernel, ONE batch per CTA (512 CTAs, ~3.5/SM, 4 co-resident) for
// latency hiding: each SMSP interleaves 3-4 independent per-step chains.
// fp16 exp-space recursion: v in smem halves, E column in 64 half2 regs,
// dot via HFMA2 into 8 accumulators combined in fp32.
// ---------------------------------------------------------------------------
__global__ __launch_bounds__(CRF_T, 4)
void crf_fused_kernel(const float* __restrict__ em,       // (B,S,T) f32
                      const void*  __restrict__ tags,     // (B,S) i32 or i64
                      const void*  __restrict__ mask,     // (B,S) i32 or u8
                      const float* __restrict__ startT,   // (T)
                      const float* __restrict__ endT,     // (T)
                      const float* __restrict__ trans,    // (T,T)
                      float* __restrict__ out)            // scalar
{
    const int b = blockIdx.x;
    const int j = threadIdx.x;
    const int lane = j & 31;
    const int warp = j >> 5;

    const float* __restrict__ emb = em + (size_t)b * CRF_S * CRF_T;

    __shared__ __align__(16) __half sV[2][CRF_T];
    __shared__ float         sRed[4];
    __shared__ float         sPart[CRF_T];
    __shared__ int           sCnt[CRF_T];
    __shared__ unsigned char sMask[CRF_S];
    __shared__ short         sTags[CRF_S];
    __shared__ int           sDet[4];
    __shared__ int           sLast;

    // ---- inline dtype detect (validated R2: mask int32 on this harness) ----
    if (j < 64) {
        const unsigned int* tw = (const unsigned int*)tags;
        const unsigned int* mw = (const unsigned int*)mask;
        const int zero = (tw[2 * j + 1] == 0u) ? 1 : 0;
        const int big  = (mw[j] > 1u) ? 1 : 0;
        const unsigned zm = __ballot_sync(0xffffffffu, zero);
        const unsigned bm = __ballot_sync(0xffffffffu, big);
        if (lane == 0) {
            sDet[warp] = __popc(zm);
            sDet[2 + warp] = __popc(bm);
        }
    }
    __syncthreads();
    const int tags_is64 = ((sDet[0] + sDet[1]) >= 48);
    const int mask_is32 = ((sDet[2] + sDet[3]) == 0);

    // ---- stage mask + tags with detected widths ----
    if (mask_is32) {
        const int* m0 = (const int*)mask + (size_t)b * CRF_S;
        for (int s = j; s < CRF_S; s += CRF_T) sMask[s] = (m0[s] != 0);
    } else {
        const unsigned char* m0 = (const unsigned char*)mask + (size_t)b * CRF_S;
        for (int s = j; s < CRF_S; s += CRF_T) sMask[s] = (m0[s] != 0);
    }
    if (tags_is64) {
        const long long* t0 = (const long long*)tags + (size_t)b * CRF_S;
        for (int s = j; s < CRF_S; s += CRF_T) sTags[s] = (short)t0[s];
    } else {
        const int* t0 = (const int*)tags + (size_t)b * CRF_S;
        for (int s = j; s < CRF_S; s += CRF_T) sTags[s] = (short)t0[s];
    }

    // ---- E column j as 64 half2 registers: Eh[k] = (E[2k][j], E[2k+1][j]) ----
    __half2 Eh[CRF_T / 2];
#pragma unroll
    for (int k = 0; k < CRF_T / 2; k++) {
        const float e0 = __expf(trans[(2 * k) * CRF_T + j]);
        const float e1 = __expf(trans[(2 * k + 1) * CRF_T + j]);
        Eh[k] = __floats2half2_rn(e0, e1);
    }

    // ---- t = 0 init: v = exp(start + em0 - m0), logZ = m0 ----
    const float m00 = startT[0] + emb[0];
    float v = __expf(startT[j] + emb[j] - m00);
    float logZ = m00;
    int   nstep = 0;

    sV[0][j] = __float2half_rn(v);

    float w = __expf(emb[CRF_T + j] - SHIFT);
    __syncthreads();

    for (int s = 1; s < CRF_S; s++) {
        const int p = (s + 1) & 1;
        const int q = s & 1;

        // branchless prefetch of next emissions (clamped; unused at s=S-1)
        const int sn = (s + 1 < CRF_S) ? (s + 1) : (CRF_S - 1);
        const float en = emb[(size_t)sn * CRF_T + j];
        const int mk = sMask[s];

        // 16 LDS.128: 128 halves of v (broadcast, conflict-free)
        const uint4* r = (const uint4*)sV[p];
        __half2 A[8];
#pragma unroll
        for (int k = 0; k < 8; k++) A[k] = __half2half2(__ushort_as_half(0));
#pragma unroll
        for (int i = 0; i < 16; i++) {
            const uint4 x = r[i];
            A[(4*i+0)&7] = __hfma2(u32_as_h2(x.x), Eh[4*i+0], A[(4*i+0)&7]);
            A[(4*i+1)&7] = __hfma2(u32_as_h2(x.y), Eh[4*i+1], A[(4*i+1)&7]);
            A[(4*i+2)&7] = __hfma2(u32_as_h2(x.z), Eh[4*i+2], A[(4*i+2)&7]);
            A[(4*i+3)&7] = __hfma2(u32_as_h2(x.w), Eh[4*i+3], A[(4*i+3)&7]);
        }
        // fp32 combine (fixed order)
        float dot;
        {
            float2 f0 = __half22float2(A[0]), f1 = __half22float2(A[1]);
            float2 f2 = __half22float2(A[2]), f3 = __half22float2(A[3]);
            float2 f4 = __half22float2(A[4]), f5 = __half22float2(A[5]);
            float2 f6 = __half22float2(A[6]), f7 = __half22float2(A[7]);
            dot = (((f0.x + f0.y) + (f1.x + f1.y)) + ((f2.x + f2.y) + (f3.x + f3.y)))
                + (((f4.x + f4.y) + (f5.x + f5.y)) + ((f6.x + f6.y) + (f7.x + f7.y)));
        }

        float vn = mk ? dot * w : v;
        nstep += mk;

        if ((s & 3) == 0) {            // rescale every 4 steps (fp16 range)
            const float cc = __half2float(sV[p][0]);
            vn *= __fdividef(1.0f, cc);
            logZ += __logf(cc);
        }

        sV[q][j] = __float2half_rn(vn);
        v = vn;

        w = __expf(en - SHIFT);
        __syncthreads();
    }
    logZ += SHIFT * (float)nstep;

    // ---- final: fwd = log(sum_j v_j * exp(end_j)) + logZ (all fp32) ----
    const float ej = __expf(endT[j]);
    float t0 = v * ej;
#pragma unroll
    for (int off = 16; off; off >>= 1)
        t0 += __shfl_xor_sync(0xffffffffu, t0, off);
    if (lane == 0) sRed[warp] = t0;
    __syncthreads();
    const float fwd = __logf((sRed[0] + sRed[1]) + (sRed[2] + sRed[3])) + logZ;

    // ---- gold score (fp32, fixed-order tree reduce) ----
    {
        float part = 0.f;
        int cnt = 0;
        for (int s = j; s < CRF_S; s += CRF_T) {
            const int mk = sMask[s] ? 1 : 0;
            cnt += mk;
            if (s >= 1 && mk) {
                const int tp = (int)sTags[s - 1];
                const int tc = (int)sTags[s];
                part += trans[tp * CRF_T + tc] + emb[(size_t)s * CRF_T + tc];
            }
        }
        sPart[j] = part;
        sCnt[j]  = cnt;
        __syncthreads();
#pragma unroll
        for (int stride = CRF_T / 2; stride > 0; stride >>= 1) {
            if (j < stride) {
                sPart[j] += sPart[j + stride];
                sCnt[j]  += sCnt[j + stride];
            }
            __syncthreads();
        }
        if (j == 0) {
            const int tg0 = (int)sTags[0];
            float gold = sPart[0] + startT[tg0] + emb[tg0];
            const int seq_end = sCnt[0] - 1;
            gold += endT[(int)sTags[seq_end]];
            g_diff[b] = fwd - gold;
        }
    }

    // ---- grid-finish: last CTA does the deterministic mean ----
    __syncthreads();
    if (j == 0) {
        __threadfence();
        const int ticket = atomicAdd(&g_arrived, 1);
        sLast = (ticket == CRF_B - 1);
    }
    __syncthreads();
    if (sLast) {
        __threadfence();
        float acc = g_diff[j] + g_diff[j + 128] + g_diff[j + 256] + g_diff[j + 384];
        sPart[j] = acc;
        __syncthreads();
#pragma unroll
        for (int stride = CRF_T / 2; stride > 0; stride >>= 1) {
            if (j < stride) sPart[j] += sPart[j + stride];
            __syncthreads();
        }
        if (j == 0) {
            out[0] = sPart[0] * (1.0f / (float)CRF_B);
            g_arrived = 0;
        }
    }
}

extern "C" void kernel_launch(void* const* d_in, const int* in_sizes, int n_in,
                              void* d_out, int out_size)
{
    const float* emissions = (const float*)d_in[0];
    const void*  tags      = d_in[1];
    const void*  mask      = d_in[2];
    const float* startT    = (const float*)d_in[3];
    const float* endT      = (const float*)d_in[4];
    const float* trans     = (const float*)d_in[5];
    float*       out       = (float*)d_out;

    crf_fused_kernel<<<CRF_B, CRF_T>>>(emissions, tags, mask,
                                       startT, endT, trans, out);
}